// round 15
// baseline (speedup 1.0000x reference)
#include <cuda_runtime.h>
#include <cstdint>

#define DTW_INF 99999.0f

// Bench size: N = M = 6144.
constexpr int MAXN = 6144;
constexpr int MAXM = 6144;
constexpr int PITCH = (MAXM + 4 + 3) & ~3;    // 6148, multiple of 4

// Diagonal-major scratch: cell (i,j) at g_buf[(i+j)*PITCH + j + 3].
__device__ float g_buf[(size_t)(MAXN + MAXM + 2) * PITCH + 16];

constexpr int SW = 128;     // strip width (columns per warp)
constexpr int W  = 4;       // columns per lane
constexpr int B  = 128;     // steps per chunk (2 chunks per launch)
constexpr int MAXSTRIPS = 64;
constexpr int HALO_PITCH = MAXN + 64;   // multiple of 4
constexpr int HSH = 2;      // halo index shift (16B-aligns batched stores)

// g_halo[s][HSH + i] = v(i, cs-1): left-boundary column of strip s.
__device__ float g_halo[(size_t)(MAXSTRIPS + 1) * HALO_PITCH];
// Persistent per-lane DP state between launches: [strip][reg 0..7][lane].
__device__ float g_state[MAXSTRIPS][2 * W][32];
// Intra-launch rendezvous: g_flag[s*32] = launch id gg once strip s finished
// its FIRST chunk of launch gg (halo rows published & fenced).
__device__ int g_flag[MAXSTRIPS * 32];

__device__ __forceinline__ size_t gidx(int d, int j) {
    return (size_t)d * PITCH + (j + 3);
}

// ---------------------------------------------------------------------------
__global__ void dtw_init(int N, int M, int nstrips)
{
    const int stride = gridDim.x * blockDim.x;
    const int idx = blockIdx.x * blockDim.x + threadIdx.x;
    for (int j = idx; j <= M; j += stride)
        g_buf[gidx(j, j)] = (j == 0) ? 0.0f : DTW_INF;
    for (int i = idx + 1; i <= N; i += stride)
        g_buf[gidx(i, 0)] = DTW_INF;
    for (int i = idx; i <= N; i += stride)
        g_halo[HSH + i] = (i == 0) ? 0.0f : DTW_INF;   // strip 0 halo (col 0)
    for (int t = idx + 1; t <= nstrips; t += stride)
        g_halo[(size_t)t * HALO_PITCH + HSH] = DTW_INF;  // v(0, cs-1)
    for (int t = idx; t < nstrips; t += stride)
        g_flag[t * 32] = -1;                           // reset per replay
}

// ---------------------------------------------------------------------------
// One anti-diagonal step. a = diag e-1 values, b = diag e-2 (overwritten with
// diag e). SINGLE shfl per step: np (neighbor diag e-2 edge) is the previous
// step's post-selection nl, carried in register pnl.
// ---------------------------------------------------------------------------
template<int E, bool ST>
__device__ __forceinline__ void phase(
    float (&a)[W], float (&b)[W], float (&xw)[W],
    const float (&yv)[W], const int (&limR)[W],
    float xn, float nh_new, float& pnl, bool is0, int lane,
    int ibase, bool hok, float* pg, float* hq, float& hsave)
{
    float nl = __shfl_up_sync(0xffffffffu, a[W - 1], 1);   // v(i0,   j0-1)
    if (is0) nl = nh_new;
    float np = pnl;                                        // v(i0-1, j0-1)
    pnl = nl;
    xw[E] = xn;

    float left = nl, diag = np;
#pragma unroll
    for (int c = 0; c < W; ++c) {
        float top = a[c], old = b[c];
        float dd = xw[(E - c) & (W - 1)] - yv[c];
        float v = fmaf(dd, dd, fminf(fminf(top, left), diag));
        if (ST) {
            b[c] = v;
        } else {
            int i = ibase - c;
            if (i >= 1 && i <= limR[c]) b[c] = v;     // freeze when inactive
        }
        diag = old; left = top;
    }

    if (ST) {
        *reinterpret_cast<float4*>(pg) = make_float4(b[0], b[1], b[2], b[3]);
        hsave = b[W - 1];
    } else {
#pragma unroll
        for (int c = 0; c < W; ++c) {
            int i = ibase - c;
            if (i >= 1 && i <= limR[c]) pg[c] = b[c];
        }
        if (lane == 31 && hok) *hq = b[W - 1];
    }
}

// ---------------------------------------------------------------------------
// Process one B-step chunk c of strip s. Self-contained: stages halo + x
// window into smem, re-derives pnl, runs steady/boundary loops.
// ---------------------------------------------------------------------------
__device__ void run_chunk(
    int c, int s, int N, int M, int lane, bool is0,
    const float* __restrict__ x,
    float (&a)[W], float (&b)[W], float (&xw)[W],
    const float (&yv)[W], const int (&limR)[W],
    float* hbuf, float (*xsw)[65])
{
    const int e0 = c * B;
    const int cs = 1 + SW * s;
    const int j0 = cs + W * lane;

    __syncwarp();   // previous chunk's smem reads complete before restaging

    // --- stage halo chunk (L2-coherent loads; producer may be same-launch) ---
    {
        const float* hsrc = g_halo + (size_t)s * HALO_PITCH + HSH;
#pragma unroll
        for (int t0 = 0; t0 < B + 8; t0 += 32) {
            int t = t0 + lane;
            if (t < B + 8) {
                int r = e0 + t; if (r > N) r = N;
                hbuf[t] = __ldcg(hsrc + r);
            }
        }
    }
    // --- stage x window: idx = e0-128 .. e0+127 ;  xsw[r][k] = x[w0+4k+r] ---
    {
        const int w0 = e0 - 128;
#pragma unroll
        for (int t0 = 0; t0 < 256; t0 += 32) {
            int t = t0 + lane;
            int idx = w0 + t;
            idx = idx < 0 ? 0 : (idx >= N ? N - 1 : idx);
            xsw[t & (W - 1)][t >> 2] = x[idx];
        }
    }
    __syncwarp();

#pragma unroll
    for (int r = 0; r < W; ++r)
        xw[r] = xsw[r][31 - lane];          // x indices e0-4*lane-4+r

    // pnl init: neighbor's diag e0-2 edge (one shfl per chunk, not per step).
    float pnl = __shfl_up_sync(0xffffffffu, b[W - 1], 1);
    if (is0) pnl = hbuf[0];

    float* pg = g_buf + gidx(cs + 1 + e0, j0);
    float* hq0 = g_halo + (size_t)(s + 1) * HALO_PITCH + HSH + (e0 - (SW - 2));

    const bool steady = (e0 >= SW) && (e0 + B <= N) && (cs + SW - 1 <= M);
    float hdum;

    if (steady) {
#pragma unroll 1
        for (int m = 0; m < B / W; ++m) {
            const int kk = 32 + m - lane;
            float xv[W], nh[W], hs[W];
#pragma unroll
            for (int r = 0; r < W; ++r) xv[r] = xsw[r][kk];
#pragma unroll
            for (int r = 0; r < W; ++r) nh[r] = hbuf[W * m + 1 + r];
            phase<0,true>(a,b,xw,yv,limR, xv[0], nh[0], pnl, is0, lane, 0, true, pg + 0*PITCH, hq0, hs[0]);
            phase<1,true>(b,a,xw,yv,limR, xv[1], nh[1], pnl, is0, lane, 0, true, pg + 1*PITCH, hq0, hs[1]);
            phase<2,true>(a,b,xw,yv,limR, xv[2], nh[2], pnl, is0, lane, 0, true, pg + 2*PITCH, hq0, hs[2]);
            phase<3,true>(b,a,xw,yv,limR, xv[3], nh[3], pnl, is0, lane, 0, true, pg + 3*PITCH, hq0, hs[3]);
            if (lane == 31) {
                *reinterpret_cast<float4*>(hq0 + W * m) =   // 16B aligned via HSH
                    make_float4(hs[0], hs[1], hs[2], hs[3]);
            }
            pg += W * PITCH;
        }
    } else {
        float* hq = hq0;
        int ib = e0 + 1 - W * lane;         // ibase at first step of chunk
#pragma unroll 1
        for (int m = 0; m < B / W; ++m) {
            const int kk = 32 + m - lane;
            float xv[W], nh[W];
#pragma unroll
            for (int r = 0; r < W; ++r) xv[r] = xsw[r][kk];
#pragma unroll
            for (int r = 0; r < W; ++r) nh[r] = hbuf[W * m + 1 + r];
            const int e = e0 + m * W;
#pragma unroll
            for (int ph = 0; ph < W; ++ph) {
                int i31 = (e + ph) - (SW - 2);
                bool hok = (i31 >= 1) && (i31 <= N);
                switch (ph) {   // compile-time unrolled: alternates a/b
                    case 0: phase<0,false>(a,b,xw,yv,limR, xv[0], nh[0], pnl, is0, lane, ib+0, hok, pg + 0*PITCH, hq, hdum); break;
                    case 1: phase<1,false>(b,a,xw,yv,limR, xv[1], nh[1], pnl, is0, lane, ib+1, hok, pg + 1*PITCH, hq, hdum); break;
                    case 2: phase<2,false>(a,b,xw,yv,limR, xv[2], nh[2], pnl, is0, lane, ib+2, hok, pg + 2*PITCH, hq, hdum); break;
                    case 3: phase<3,false>(b,a,xw,yv,limR, xv[3], nh[3], pnl, is0, lane, ib+3, hok, pg + 3*PITCH, hq, hdum); break;
                }
                ++hq;
            }
            pg += W * PITCH;
            ib += W;
        }
    }
}

// ---------------------------------------------------------------------------
// Dual-chunk kernel: launch gg advances strip s = s0 + blockIdx.x by chunks
// (c0, c0+1), c0 = 2*(gg - s). Chunk c0's inputs come from the previous
// launch (PDL gridsync); chunk c0+1 additionally needs the producer strip's
// FIRST chunk of THIS launch -> single flag rendezvous.
// ---------------------------------------------------------------------------
__global__ __launch_bounds__(32, 1)
void dtw_chunk2(const float* __restrict__ x, const float* __restrict__ y,
                int N, int M, int gg, int s0, int nstrips)
{
#if __CUDA_ARCH__ >= 900
    cudaTriggerProgrammaticLaunchCompletion();
#endif

    const int s = s0 + blockIdx.x;
    const int nchunks = (N + SW + B - 1) / B;     // 49
    const int cp = gg - s;                        // chunk-pair index
    const int c0 = 2 * cp;

    __shared__ float hbuf[B + 8];
    __shared__ float xsw[W][65];

    const int lane = threadIdx.x;
    const int cs = 1 + SW * s;
    const int j0 = cs + W * lane;
    const bool is0 = (lane == 0);

    // --- predecessor-independent prologue ---
    float yv[W]; int limR[W];
#pragma unroll
    for (int q = 0; q < W; ++q) {
        bool ok = (j0 + q) <= M;
        yv[q] = ok ? y[j0 + q - 1] : 0.0f;
        limR[q] = ok ? N : 0;
    }

#if __CUDA_ARCH__ >= 900
    cudaGridDependencySynchronize();    // previous launch's writes visible
#endif

    if (cp < 0 || c0 >= nchunks) return;

    // --- DP state ---
    float a[W], b[W], xw[W];
    if (c0 == 0) {
#pragma unroll
        for (int q = 0; q < W; ++q) { a[q] = DTW_INF; b[q] = DTW_INF; }
    } else {
#pragma unroll
        for (int q = 0; q < W; ++q) {
            a[q] = g_state[s][q][lane];
            b[q] = g_state[s][W + q][lane];
        }
    }

    // ---- first chunk (inputs all from previous launches) ----
    run_chunk(c0, s, N, M, lane, is0, x, a, b, xw, yv, limR, hbuf, xsw);

    // ---- publish: halo rows of chunk c0 are written by lane 31 ----
    if (lane == 31 && s + 1 < nstrips) {
        __threadfence();
        *(volatile int*)&g_flag[s * 32] = gg;
    }

    // ---- second chunk (needs producer's first chunk of THIS launch) ----
    const int c1 = c0 + 1;
    if (c1 < nchunks) {
        if (s > 0) {
            if (is0) {
                while (*(volatile int*)&g_flag[(s - 1) * 32] < gg)
                    __nanosleep(32);
                __threadfence();
            }
            __syncwarp();
        }
        run_chunk(c1, s, N, M, lane, is0, x, a, b, xw, yv, limR, hbuf, xsw);
    }

    // --- persist DP state ---
#pragma unroll
    for (int q = 0; q < W; ++q) {
        g_state[s][q][lane]     = a[q];
        g_state[s][W + q][lane] = b[q];
    }
}

// ---------------------------------------------------------------------------
// De-skew + sqrt: out[i][j] = sqrt(g_buf[gidx(i+j, j)]).
// ---------------------------------------------------------------------------
constexpr int TR = 128;
constexpr int TC = 32;

__global__ __launch_bounds__(256)
void dtw_deskew(float* __restrict__ out, int N, int M)
{
    __shared__ float sh[TR + TC - 1][TC];
    const int i0 = blockIdx.y * TR;
    const int j0 = blockIdx.x * TC;
    const int d0 = i0 + j0;
    const int pitch_out = M + 1;

    for (int k = threadIdx.x; k < (TR + TC - 1) * TC; k += 256) {
        int dl = k >> 5;
        int jl = k & 31;
        int dg = d0 + dl;
        int jg = j0 + jl;
        float v = 0.0f;
        if (dg <= N + M && jg <= M)
            v = g_buf[gidx(dg, jg)];
        sh[dl][jl] = v;
    }
    __syncthreads();

    for (int k = threadIdx.x; k < TR * TC; k += 256) {
        int ii = k >> 5;
        int jl = k & 31;
        int ig = i0 + ii;
        int jg = j0 + jl;
        if (ig <= N && jg <= M)
            out[(size_t)ig * pitch_out + jg] = sqrtf(sh[ii + jl][jl]);
    }
}

// ---------------------------------------------------------------------------
extern "C" void kernel_launch(void* const* d_in, const int* in_sizes, int n_in,
                              void* d_out, int out_size)
{
    const float* x = (const float*)d_in[0];
    const float* y = (const float*)d_in[1];
    float* out = (float*)d_out;
    const int N = in_sizes[0];
    const int M = in_sizes[1];

    const int nstrips = (M + SW - 1) / SW;            // 48
    const int nchunks = (N + SW + B - 1) / B;         // 49
    const int npair = (nchunks + 1) / 2;              // 25
    const int G = (npair - 1) + (nstrips - 1) + 1;    // 72

    dtw_init<<<64, 256>>>(N, M, nstrips);

    cudaLaunchAttribute attrs[1];
    attrs[0].id = cudaLaunchAttributeProgrammaticStreamSerialization;
    attrs[0].val.programmaticStreamSerializationAllowed = 1;

    for (int gg = 0; gg < G; ++gg) {
        int s_min = gg - (npair - 1); if (s_min < 0) s_min = 0;
        int s_max = gg; if (s_max > nstrips - 1) s_max = nstrips - 1;
        if (s_max < s_min) continue;

        cudaLaunchConfig_t cfg = {};
        cfg.gridDim = dim3(s_max - s_min + 1, 1, 1);
        cfg.blockDim = dim3(32, 1, 1);
        cfg.dynamicSmemBytes = 0;
        cfg.stream = 0;
        cfg.attrs = attrs;
        cfg.numAttrs = 1;
        cudaLaunchKernelEx(&cfg, dtw_chunk2, x, y, N, M, gg, s_min, nstrips);
    }

    dim3 grid((M + 1 + TC - 1) / TC, (N + 1 + TR - 1) / TR);
    dtw_deskew<<<grid, 256>>>(out, N, M);
}

// round 16
// speedup vs baseline: 1.5455x; 1.5455x over previous
#include <cuda_runtime.h>
#include <cstdint>

#define DTW_INF 99999.0f

// Bench size: N = M = 6144.
constexpr int MAXN = 6144;
constexpr int MAXM = 6144;
constexpr int PITCH = (MAXM + 4 + 3) & ~3;    // 6148, multiple of 4

// Diagonal-major scratch: cell (i,j) at g_buf[(i+j)*PITCH + j + 3].
__device__ float g_buf[(size_t)(MAXN + MAXM + 2) * PITCH + 16];

constexpr int SW = 128;     // strip width (columns per warp)
constexpr int W  = 4;       // columns per lane
constexpr int B  = 128;     // steps per launch-chunk
constexpr int LAG = 2;      // chunk lag between strips; B*(LAG-1) >= SW-1
constexpr int MAXSTRIPS = 64;
constexpr int HALO_PITCH = MAXN + 64;   // multiple of 4
constexpr int HSH = 2;      // halo index shift (16B-aligns batched stores)

// g_halo[s][HSH + i] = v(i, cs-1): left-boundary column of strip s.
__device__ float g_halo[(size_t)(MAXSTRIPS + 1) * HALO_PITCH];
// Persistent per-lane DP state between launches: [strip][reg 0..7][lane].
__device__ float g_state[MAXSTRIPS][2 * W][32];

// Deskew tiling of the output.
constexpr int TR = 128;
constexpr int TC = 32;

__device__ __forceinline__ size_t gidx(int d, int j) {
    return (size_t)d * PITCH + (j + 3);
}

// Tile (ty,tx) band membership: q_t = min(qmax, (128*ty + 32*tx + 156)/128).
// For band q (< qmax): tx in [4*(q-ty)-4, 4*(q-ty)-1]; band qmax is catch-all.
__host__ __device__ inline void band_range(int q, int ty, int qmax, int ntx,
                                           int& lo, int& hi) {
    int D = q - ty;
    lo = 4 * D - 4;
    hi = (q == qmax) ? (ntx - 1) : (4 * D - 1);
    if (lo < 0) lo = 0;
    if (hi > ntx - 1) hi = ntx - 1;
}

// ---------------------------------------------------------------------------
__global__ void dtw_init(int N, int M, int nstrips)
{
    const int stride = gridDim.x * blockDim.x;
    const int idx = blockIdx.x * blockDim.x + threadIdx.x;
    for (int j = idx; j <= M; j += stride)
        g_buf[gidx(j, j)] = (j == 0) ? 0.0f : DTW_INF;
    for (int i = idx + 1; i <= N; i += stride)
        g_buf[gidx(i, 0)] = DTW_INF;
    for (int i = idx; i <= N; i += stride)
        g_halo[HSH + i] = (i == 0) ? 0.0f : DTW_INF;   // strip 0 halo (col 0)
    for (int t = idx + 1; t <= nstrips; t += stride)
        g_halo[(size_t)t * HALO_PITCH + HSH] = DTW_INF;  // v(0, cs-1)
}

// ---------------------------------------------------------------------------
// One anti-diagonal step. a = diag e-1 values, b = diag e-2 (overwritten with
// diag e). SINGLE shfl per step: np (neighbor diag e-2 edge) is the previous
// step's post-selection nl, carried in register pnl.
// ---------------------------------------------------------------------------
template<int E, bool ST>
__device__ __forceinline__ void phase(
    float (&a)[W], float (&b)[W], float (&xw)[W],
    const float (&yv)[W], const int (&limR)[W],
    float xn, float nh_new, float& pnl, bool is0, int lane,
    int ibase, bool hok, float* pg, float* hq, float& hsave)
{
    float nl = __shfl_up_sync(0xffffffffu, a[W - 1], 1);   // v(i0,   j0-1)
    if (is0) nl = nh_new;
    float np = pnl;                                        // v(i0-1, j0-1)
    pnl = nl;
    xw[E] = xn;

    float left = nl, diag = np;
#pragma unroll
    for (int c = 0; c < W; ++c) {
        float top = a[c], old = b[c];
        float dd = xw[(E - c) & (W - 1)] - yv[c];
        float v = fmaf(dd, dd, fminf(fminf(top, left), diag));
        if (ST) {
            b[c] = v;
        } else {
            int i = ibase - c;
            if (i >= 1 && i <= limR[c]) b[c] = v;     // freeze when inactive
        }
        diag = old; left = top;
    }

    if (ST) {
        *reinterpret_cast<float4*>(pg) = make_float4(b[0], b[1], b[2], b[3]);
        hsave = b[W - 1];
    } else {
#pragma unroll
        for (int c = 0; c < W; ++c) {
            int i = ibase - c;
            if (i >= 1 && i <= limR[c]) pg[c] = b[c];
        }
        if (lane == 31 && hok) *hq = b[W - 1];
    }
}

// ---------------------------------------------------------------------------
// Fused kernel. Blocks [0, nwave): wave chunk for strip s = s0 + blockIdx
// (chunk c = gg - 2s), exactly the proven R14 path (warp 0 only).
// Blocks [nwave, nwave+ndesk): deskew one output tile of band bq (tiles whose
// inputs completed by launch gg-1; PDL gridsync provides ordering).
// ---------------------------------------------------------------------------
__global__ __launch_bounds__(256, 1)
void dtw_mega(const float* __restrict__ x, const float* __restrict__ y,
              float* __restrict__ out, int N, int M,
              int gg, int s0, int nwave, int bq, int qmax, int nty, int ntx)
{
#if __CUDA_ARCH__ >= 900
    cudaTriggerProgrammaticLaunchCompletion();
#endif

    if ((int)blockIdx.x < nwave) {
        // ================= wave path (R14, unchanged) =================
        if (threadIdx.x >= 32) return;

        const int s = s0 + blockIdx.x;
        const int nchunks = (N + SW + B - 1) / B;
        const int c = gg - LAG * s;

        __shared__ float hbuf[B + 8];
        __shared__ float xsw[W][65];

        const int lane = threadIdx.x;
        const int e0 = (c < 0 ? 0 : c) * B;
        const int cs = 1 + SW * s;
        const int j0 = cs + W * lane;
        const bool is0 = (lane == 0);

        // --- predecessor-independent prologue: x window + y ---
        {
            const int w0 = e0 - 128;
#pragma unroll
            for (int t0 = 0; t0 < 256; t0 += 32) {
                int t = t0 + lane;
                int idx = w0 + t;
                idx = idx < 0 ? 0 : (idx >= N ? N - 1 : idx);
                xsw[t & (W - 1)][t >> 2] = x[idx];
            }
        }
        float yv[W]; int limR[W];
#pragma unroll
        for (int q = 0; q < W; ++q) {
            bool ok = (j0 + q) <= M;
            yv[q] = ok ? y[j0 + q - 1] : 0.0f;
            limR[q] = ok ? N : 0;
        }

#if __CUDA_ARCH__ >= 900
        cudaGridDependencySynchronize();
#endif

        if (c < 0 || c >= nchunks) return;

        // --- stage halo chunk ---
        {
            const float* hsrc = g_halo + (size_t)s * HALO_PITCH + HSH;
#pragma unroll
            for (int t0 = 0; t0 < B + 8; t0 += 32) {
                int t = t0 + lane;
                if (t < B + 8) {
                    int r = e0 + t; if (r > N) r = N;
                    hbuf[t] = hsrc[r];
                }
            }
        }
        __syncwarp();

        // --- DP state ---
        float a[W], b[W], xw[W];
        if (c == 0) {
#pragma unroll
            for (int q = 0; q < W; ++q) { a[q] = DTW_INF; b[q] = DTW_INF; }
        } else {
#pragma unroll
            for (int q = 0; q < W; ++q) {
                a[q] = g_state[s][q][lane];
                b[q] = g_state[s][W + q][lane];
            }
        }
#pragma unroll
        for (int r = 0; r < W; ++r)
            xw[r] = xsw[r][31 - lane];

        float pnl = __shfl_up_sync(0xffffffffu, b[W - 1], 1);
        if (is0) pnl = hbuf[0];

        float* pg = g_buf + gidx(cs + 1 + e0, j0);
        float* hq0 = g_halo + (size_t)(s + 1) * HALO_PITCH + HSH + (e0 - (SW - 2));

        const bool steady = (e0 >= SW) && (e0 + B <= N) && (cs + SW - 1 <= M);
        float hdum;

        if (steady) {
#pragma unroll 1
            for (int m = 0; m < B / W; ++m) {
                const int kk = 32 + m - lane;
                float xv[W], nh[W], hs[W];
#pragma unroll
                for (int r = 0; r < W; ++r) xv[r] = xsw[r][kk];
#pragma unroll
                for (int r = 0; r < W; ++r) nh[r] = hbuf[W * m + 1 + r];
                phase<0,true>(a,b,xw,yv,limR, xv[0], nh[0], pnl, is0, lane, 0, true, pg + 0*PITCH, hq0, hs[0]);
                phase<1,true>(b,a,xw,yv,limR, xv[1], nh[1], pnl, is0, lane, 0, true, pg + 1*PITCH, hq0, hs[1]);
                phase<2,true>(a,b,xw,yv,limR, xv[2], nh[2], pnl, is0, lane, 0, true, pg + 2*PITCH, hq0, hs[2]);
                phase<3,true>(b,a,xw,yv,limR, xv[3], nh[3], pnl, is0, lane, 0, true, pg + 3*PITCH, hq0, hs[3]);
                if (lane == 31) {
                    *reinterpret_cast<float4*>(hq0 + W * m) =
                        make_float4(hs[0], hs[1], hs[2], hs[3]);
                }
                pg += W * PITCH;
            }
        } else {
            float* hq = hq0;
            int ib = e0 + 1 - W * lane;
#pragma unroll 1
            for (int m = 0; m < B / W; ++m) {
                const int kk = 32 + m - lane;
                float xv[W], nh[W];
#pragma unroll
                for (int r = 0; r < W; ++r) xv[r] = xsw[r][kk];
#pragma unroll
                for (int r = 0; r < W; ++r) nh[r] = hbuf[W * m + 1 + r];
                const int e = e0 + m * W;
#pragma unroll
                for (int ph = 0; ph < W; ++ph) {
                    int i31 = (e + ph) - (SW - 2);
                    bool hok = (i31 >= 1) && (i31 <= N);
                    switch (ph) {
                        case 0: phase<0,false>(a,b,xw,yv,limR, xv[0], nh[0], pnl, is0, lane, ib+0, hok, pg + 0*PITCH, hq, hdum); break;
                        case 1: phase<1,false>(b,a,xw,yv,limR, xv[1], nh[1], pnl, is0, lane, ib+1, hok, pg + 1*PITCH, hq, hdum); break;
                        case 2: phase<2,false>(a,b,xw,yv,limR, xv[2], nh[2], pnl, is0, lane, ib+2, hok, pg + 2*PITCH, hq, hdum); break;
                        case 3: phase<3,false>(b,a,xw,yv,limR, xv[3], nh[3], pnl, is0, lane, ib+3, hok, pg + 3*PITCH, hq, hdum); break;
                    }
                    ++hq;
                }
                pg += W * PITCH;
                ib += W;
            }
        }

#pragma unroll
        for (int q = 0; q < W; ++q) {
            g_state[s][q][lane]     = a[q];
            g_state[s][W + q][lane] = b[q];
        }
        return;
    }

    // ================= deskew path =================
    if (bq < 0) return;
    {
        // Locate this block's tile within band bq (rank-order over ty).
        int rank = (int)blockIdx.x - nwave;
        int ty = -1, tx = -1;
        for (int t = 0; t < nty; ++t) {
            int lo, hi;
            band_range(bq, t, qmax, ntx, lo, hi);
            int cnt = hi - lo + 1; if (cnt < 0) cnt = 0;
            if (rank < cnt) { ty = t; tx = lo + rank; break; }
            rank -= cnt;
        }

#if __CUDA_ARCH__ >= 900
        cudaGridDependencySynchronize();   // band inputs written by launch gg-1
#endif
        if (ty < 0) return;

        __shared__ float sh[TR + TC - 1][TC];
        const int i0 = ty * TR;
        const int j0 = tx * TC;
        const int d0 = i0 + j0;
        const int pitch_out = M + 1;

        for (int k = threadIdx.x; k < (TR + TC - 1) * TC; k += 256) {
            int dl = k >> 5;
            int jl = k & 31;
            int dg = d0 + dl;
            int jg = j0 + jl;
            float v = 0.0f;
            if (dg <= N + M && jg <= M)
                v = g_buf[gidx(dg, jg)];
            sh[dl][jl] = v;
        }
        __syncthreads();

        for (int k = threadIdx.x; k < TR * TC; k += 256) {
            int ii = k >> 5;
            int jl = k & 31;
            int ig = i0 + ii;
            int jg = j0 + jl;
            if (ig <= N && jg <= M)
                out[(size_t)ig * pitch_out + jg] = sqrtf(sh[ii + jl][jl]);
        }
    }
}

// ---------------------------------------------------------------------------
extern "C" void kernel_launch(void* const* d_in, const int* in_sizes, int n_in,
                              void* d_out, int out_size)
{
    const float* x = (const float*)d_in[0];
    const float* y = (const float*)d_in[1];
    float* out = (float*)d_out;
    const int N = in_sizes[0];
    const int M = in_sizes[1];

    const int nstrips = (M + SW - 1) / SW;            // 48
    const int nchunks = (N + SW + B - 1) / B;         // 49
    const int G = (nchunks - 1) + LAG * (nstrips - 1) + 1;   // 143

    const int nty = (N + 1 + TR - 1) / TR;            // 49
    const int ntx = (M + 1 + TC - 1) / TC;            // 193
    const int qmax = (N + M - 2) / 128;               // 95
    const int smax_clamp = nstrips - 1;               // 47

    dtw_init<<<64, 256>>>(N, M, nstrips);

    cudaLaunchAttribute attrs[1];
    attrs[0].id = cudaLaunchAttributeProgrammaticStreamSerialization;
    attrs[0].val.programmaticStreamSerializationAllowed = 1;

    const int G2 = qmax + smax_clamp + 2;             // 144: last band's launch + 1
    for (int gg = 0; gg < G2; ++gg) {
        // wave blocks
        int nwave = 0, s_min = 0;
        if (gg < G) {
            s_min = (gg - (nchunks - 1) + LAG - 1) / LAG;
            if (s_min < 0) s_min = 0;
            int s_max = gg / LAG;
            if (s_max > nstrips - 1) s_max = nstrips - 1;
            if (s_max >= s_min) nwave = s_max - s_min + 1;
        }

        // deskew band for this launch: band q processed at gg = q + min(47,q) + 1
        int bq = -1;
        if (gg >= 1) {
            if (gg <= 2 * smax_clamp + 1) {
                if (gg & 1) bq = (gg - 1) / 2;
            } else {
                int q = gg - smax_clamp - 1;
                if (q <= qmax) bq = q;
            }
        }
        int ndesk = 0;
        if (bq >= 0) {
            for (int t = 0; t < nty; ++t) {
                int lo, hi;
                band_range(bq, t, qmax, ntx, lo, hi);
                int cnt = hi - lo + 1;
                if (cnt > 0) ndesk += cnt;
            }
            if (ndesk == 0) bq = -1;
        }

        int grid = nwave + ndesk;
        if (grid == 0) continue;

        cudaLaunchConfig_t cfg = {};
        cfg.gridDim = dim3(grid, 1, 1);
        cfg.blockDim = dim3(256, 1, 1);
        cfg.dynamicSmemBytes = 0;
        cfg.stream = 0;
        cfg.attrs = attrs;
        cfg.numAttrs = 1;
        cudaLaunchKernelEx(&cfg, dtw_mega, x, y, out, N, M,
                           gg, s_min, nwave, bq, qmax, nty, ntx);
    }
}

// round 17
// speedup vs baseline: 2.6603x; 1.7213x over previous
#include <cuda_runtime.h>
#include <cstdint>

#define DTW_INF 99999.0f

// Bench size: N = M = 6144.
constexpr int MAXN = 6144;
constexpr int MAXM = 6144;
constexpr int PITCH = (MAXM + 4 + 3) & ~3;    // 6148, multiple of 4

// Diagonal-major scratch: cell (i,j) at g_buf[(i+j)*PITCH + j + 3].
__device__ float g_buf[(size_t)(MAXN + MAXM + 2) * PITCH + 16];

constexpr int SW = 128;     // strip width (columns per warp)
constexpr int W  = 4;       // columns per lane
constexpr int B  = 128;     // steps per launch-chunk
constexpr int LAG = 2;      // chunk lag between strips; B*(LAG-1) >= SW-1
constexpr int MAXSTRIPS = 64;
constexpr int HALO_PITCH = MAXN + 64;   // multiple of 4
constexpr int HSH = 2;      // halo index shift (16B-aligns batched stores)

// g_halo[s][HSH + i] = v(i, cs-1): left-boundary column of strip s.
__device__ float g_halo[(size_t)(MAXSTRIPS + 1) * HALO_PITCH];
// Persistent per-lane DP state between launches: [strip][reg 0..7][lane].
__device__ float g_state[MAXSTRIPS][2 * W][32];

// Deskew tiling of the output.
constexpr int TR = 128;
constexpr int TC = 32;

__device__ __forceinline__ size_t gidx(int d, int j) {
    return (size_t)d * PITCH + (j + 3);
}

// Tile (ty,tx) band membership: q_t = min(qmax, (128*ty + 32*tx + 156)/128).
// For band q (< qmax): tx in [4*(q-ty)-4, 4*(q-ty)-1]; band qmax is catch-all.
__host__ __device__ inline void band_range(int q, int ty, int qmax, int ntx,
                                           int& lo, int& hi) {
    int D = q - ty;
    lo = 4 * D - 4;
    hi = (q == qmax) ? (ntx - 1) : (4 * D - 1);
    if (lo < 0) lo = 0;
    if (hi > ntx - 1) hi = ntx - 1;
}

// ---------------------------------------------------------------------------
__global__ void dtw_init(int N, int M, int nstrips)
{
    const int stride = gridDim.x * blockDim.x;
    const int idx = blockIdx.x * blockDim.x + threadIdx.x;
    for (int j = idx; j <= M; j += stride)
        g_buf[gidx(j, j)] = (j == 0) ? 0.0f : DTW_INF;
    for (int i = idx + 1; i <= N; i += stride)
        g_buf[gidx(i, 0)] = DTW_INF;
    for (int i = idx; i <= N; i += stride)
        g_halo[HSH + i] = (i == 0) ? 0.0f : DTW_INF;   // strip 0 halo (col 0)
    for (int t = idx + 1; t <= nstrips; t += stride)
        g_halo[(size_t)t * HALO_PITCH + HSH] = DTW_INF;  // v(0, cs-1)
}

// ---------------------------------------------------------------------------
// One anti-diagonal step. a = diag e-1 values, b = diag e-2 (overwritten with
// diag e). SINGLE shfl per step: np (neighbor diag e-2 edge) is the previous
// step's post-selection nl, carried in register pnl.
// ---------------------------------------------------------------------------
template<int E, bool ST>
__device__ __forceinline__ void phase(
    float (&a)[W], float (&b)[W], float (&xw)[W],
    const float (&yv)[W], const int (&limR)[W],
    float xn, float nh_new, float& pnl, bool is0, int lane,
    int ibase, bool hok, float* pg, float* hq, float& hsave)
{
    float nl = __shfl_up_sync(0xffffffffu, a[W - 1], 1);   // v(i0,   j0-1)
    if (is0) nl = nh_new;
    float np = pnl;                                        // v(i0-1, j0-1)
    pnl = nl;
    xw[E] = xn;

    float left = nl, diag = np;
#pragma unroll
    for (int c = 0; c < W; ++c) {
        float top = a[c], old = b[c];
        float dd = xw[(E - c) & (W - 1)] - yv[c];
        float v = fmaf(dd, dd, fminf(fminf(top, left), diag));
        if (ST) {
            b[c] = v;
        } else {
            int i = ibase - c;
            if (i >= 1 && i <= limR[c]) b[c] = v;     // freeze when inactive
        }
        diag = old; left = top;
    }

    if (ST) {
        *reinterpret_cast<float4*>(pg) = make_float4(b[0], b[1], b[2], b[3]);
        hsave = b[W - 1];
    } else {
#pragma unroll
        for (int c = 0; c < W; ++c) {
            int i = ibase - c;
            if (i >= 1 && i <= limR[c]) pg[c] = b[c];
        }
        if (lane == 31 && hok) *hq = b[W - 1];
    }
}

// ---------------------------------------------------------------------------
// Chunk-diagonal kernel with PDL (R14, unchanged): launch g advances strip
// s = s0 + blockIdx.x by B steps on chunk c = g - LAG*s.
// ---------------------------------------------------------------------------
__global__ __launch_bounds__(32, 1)
void dtw_chunk(const float* __restrict__ x, const float* __restrict__ y,
               int N, int M, int g, int s0)
{
#if __CUDA_ARCH__ >= 900
    cudaTriggerProgrammaticLaunchCompletion();
#endif

    const int s = s0 + blockIdx.x;
    const int nchunks = (N + SW + B - 1) / B;
    const int c = g - LAG * s;

    __shared__ float hbuf[B + 8];       // halo rows e0..e0+B (+slack)
    __shared__ float xsw[W][65];        // x window, residue-deinterleaved

    const int lane = threadIdx.x;
    const int e0 = (c < 0 ? 0 : c) * B;
    const int cs = 1 + SW * s;
    const int j0 = cs + W * lane;
    const bool is0 = (lane == 0);

    // --- prologue independent of predecessor: x window + y ---
    {
        const int w0 = e0 - 128;
#pragma unroll
        for (int t0 = 0; t0 < 256; t0 += 32) {
            int t = t0 + lane;
            int idx = w0 + t;
            idx = idx < 0 ? 0 : (idx >= N ? N - 1 : idx);
            xsw[t & (W - 1)][t >> 2] = x[idx];
        }
    }
    float yv[W]; int limR[W];
#pragma unroll
    for (int q = 0; q < W; ++q) {
        bool ok = (j0 + q) <= M;
        yv[q] = ok ? y[j0 + q - 1] : 0.0f;
        limR[q] = ok ? N : 0;
    }

#if __CUDA_ARCH__ >= 900
    cudaGridDependencySynchronize();    // predecessor writes now visible
#endif

    if (c < 0 || c >= nchunks) return;

    // --- stage halo chunk (written by strip s-1 in earlier launches) ---
    {
        const float* hsrc = g_halo + (size_t)s * HALO_PITCH + HSH;
#pragma unroll
        for (int t0 = 0; t0 < B + 8; t0 += 32) {
            int t = t0 + lane;
            if (t < B + 8) {
                int r = e0 + t; if (r > N) r = N;
                hbuf[t] = hsrc[r];
            }
        }
    }
    __syncwarp();

    // --- DP state ---
    float a[W], b[W], xw[W];
    if (c == 0) {
#pragma unroll
        for (int q = 0; q < W; ++q) { a[q] = DTW_INF; b[q] = DTW_INF; }
    } else {
#pragma unroll
        for (int q = 0; q < W; ++q) {
            a[q] = g_state[s][q][lane];
            b[q] = g_state[s][W + q][lane];
        }
    }
#pragma unroll
    for (int r = 0; r < W; ++r)
        xw[r] = xsw[r][31 - lane];          // x indices e0-4*lane-4+r

    // pnl init: neighbor's diag e0-2 edge (one shfl per chunk, not per step).
    float pnl = __shfl_up_sync(0xffffffffu, b[W - 1], 1);
    if (is0) pnl = hbuf[0];

    float* pg = g_buf + gidx(cs + 1 + e0, j0);
    float* hq0 = g_halo + (size_t)(s + 1) * HALO_PITCH + HSH + (e0 - (SW - 2));

    const bool steady = (e0 >= SW) && (e0 + B <= N) && (cs + SW - 1 <= M);
    float hdum;

    if (steady) {
#pragma unroll 1
        for (int m = 0; m < B / W; ++m) {
            const int kk = 32 + m - lane;
            float xv[W], nh[W], hs[W];
#pragma unroll
            for (int r = 0; r < W; ++r) xv[r] = xsw[r][kk];
#pragma unroll
            for (int r = 0; r < W; ++r) nh[r] = hbuf[W * m + 1 + r];
            phase<0,true>(a,b,xw,yv,limR, xv[0], nh[0], pnl, is0, lane, 0, true, pg + 0*PITCH, hq0, hs[0]);
            phase<1,true>(b,a,xw,yv,limR, xv[1], nh[1], pnl, is0, lane, 0, true, pg + 1*PITCH, hq0, hs[1]);
            phase<2,true>(a,b,xw,yv,limR, xv[2], nh[2], pnl, is0, lane, 0, true, pg + 2*PITCH, hq0, hs[2]);
            phase<3,true>(b,a,xw,yv,limR, xv[3], nh[3], pnl, is0, lane, 0, true, pg + 3*PITCH, hq0, hs[3]);
            if (lane == 31) {
                *reinterpret_cast<float4*>(hq0 + W * m) =   // 16B aligned via HSH
                    make_float4(hs[0], hs[1], hs[2], hs[3]);
            }
            pg += W * PITCH;
        }
    } else {
        float* hq = hq0;
        int ib = e0 + 1 - W * lane;         // ibase at first step of chunk
#pragma unroll 1
        for (int m = 0; m < B / W; ++m) {
            const int kk = 32 + m - lane;
            float xv[W], nh[W];
#pragma unroll
            for (int r = 0; r < W; ++r) xv[r] = xsw[r][kk];
#pragma unroll
            for (int r = 0; r < W; ++r) nh[r] = hbuf[W * m + 1 + r];
            const int e = e0 + m * W;
#pragma unroll
            for (int ph = 0; ph < W; ++ph) {
                int i31 = (e + ph) - (SW - 2);
                bool hok = (i31 >= 1) && (i31 <= N);
                switch (ph) {   // compile-time unrolled: alternates a/b
                    case 0: phase<0,false>(a,b,xw,yv,limR, xv[0], nh[0], pnl, is0, lane, ib+0, hok, pg + 0*PITCH, hq, hdum); break;
                    case 1: phase<1,false>(b,a,xw,yv,limR, xv[1], nh[1], pnl, is0, lane, ib+1, hok, pg + 1*PITCH, hq, hdum); break;
                    case 2: phase<2,false>(a,b,xw,yv,limR, xv[2], nh[2], pnl, is0, lane, ib+2, hok, pg + 2*PITCH, hq, hdum); break;
                    case 3: phase<3,false>(b,a,xw,yv,limR, xv[3], nh[3], pnl, is0, lane, ib+3, hok, pg + 3*PITCH, hq, hdum); break;
                }
                ++hq;
            }
            pg += W * PITCH;
            ib += W;
        }
    }

    // --- persist DP state for the next chunk of this strip ---
#pragma unroll
    for (int q = 0; q < W; ++q) {
        g_state[s][q][lane]     = a[q];
        g_state[s][W + q][lane] = b[q];
    }
}

// ---------------------------------------------------------------------------
// Deskew band batch (runs on a SEPARATE stream, gated by events):
// blockIdx.y selects band q = q0 + y; blockIdx.x is the tile rank in band q.
// out[i][j] = sqrt(g_buf[gidx(i+j, j)]).
// ---------------------------------------------------------------------------
__global__ __launch_bounds__(256)
void dtw_deskew_band(float* __restrict__ out, int N, int M,
                     int q0, int qmax, int nty, int ntx)
{
    const int q = q0 + (int)blockIdx.y;
    if (q > qmax) return;

    // Locate this block's tile within band q (rank-order over ty).
    int rank = (int)blockIdx.x;
    int ty = -1, tx = -1;
    for (int t = 0; t < nty; ++t) {
        int lo, hi;
        band_range(q, t, qmax, ntx, lo, hi);
        int cnt = hi - lo + 1; if (cnt < 0) cnt = 0;
        if (rank < cnt) { ty = t; tx = lo + rank; break; }
        rank -= cnt;
    }
    if (ty < 0) return;

    __shared__ float sh[TR + TC - 1][TC];
    const int i0 = ty * TR;
    const int j0 = tx * TC;
    const int d0 = i0 + j0;
    const int pitch_out = M + 1;

    for (int k = threadIdx.x; k < (TR + TC - 1) * TC; k += 256) {
        int dl = k >> 5;
        int jl = k & 31;
        int dg = d0 + dl;
        int jg = j0 + jl;
        float v = 0.0f;
        if (dg <= N + M && jg <= M)
            v = g_buf[gidx(dg, jg)];
        sh[dl][jl] = v;
    }
    __syncthreads();

    for (int k = threadIdx.x; k < TR * TC; k += 256) {
        int ii = k >> 5;
        int jl = k & 31;
        int ig = i0 + ii;
        int jg = j0 + jl;
        if (ig <= N && jg <= M)
            out[(size_t)ig * pitch_out + jg] = sqrtf(sh[ii + jl][jl]);
    }
}

// ---------------------------------------------------------------------------
extern "C" void kernel_launch(void* const* d_in, const int* in_sizes, int n_in,
                              void* d_out, int out_size)
{
    const float* x = (const float*)d_in[0];
    const float* y = (const float*)d_in[1];
    float* out = (float*)d_out;
    const int N = in_sizes[0];
    const int M = in_sizes[1];

    const int nstrips = (M + SW - 1) / SW;            // 48
    const int nchunks = (N + SW + B - 1) / B;         // 49
    const int G = (nchunks - 1) + LAG * (nstrips - 1) + 1;   // 143

    const int nty = (N + 1 + TR - 1) / TR;            // 49
    const int ntx = (M + 1 + TC - 1) / TC;            // 193
    const int qmax = (N + M - 2) / 128;               // 95
    const int smax_clamp = nstrips - 1;               // 47

    constexpr int NB = 12;        // deskew batches (8 bands each)

    // Lazily-created side stream + events (first call is the un-captured
    // correctness run; work per call is identical every call).
    static cudaStream_t s2 = nullptr;
    static cudaEvent_t evb[NB];
    static cudaEvent_t evj = nullptr;
    if (s2 == nullptr) {
        cudaStreamCreateWithFlags(&s2, cudaStreamNonBlocking);
        for (int k = 0; k < NB; ++k)
            cudaEventCreateWithFlags(&evb[k], cudaEventDisableTiming);
        cudaEventCreateWithFlags(&evj, cudaEventDisableTiming);
    }

    // Gate launch index for batch k (bands 8k .. 8k+7): band q is complete
    // once wave launch q + min(47, q) has fully finished (R16-verified).
    int gate[NB];
    for (int k = 0; k < NB; ++k) {
        int q_hi = 8 * k + 7; if (q_hi > qmax) q_hi = qmax;
        int gg = q_hi + (q_hi < smax_clamp ? q_hi : smax_clamp);
        if (gg > G - 1) gg = G - 1;
        gate[k] = gg;
    }

    dtw_init<<<64, 256>>>(N, M, nstrips);

    cudaLaunchAttribute attrs[1];
    attrs[0].id = cudaLaunchAttributeProgrammaticStreamSerialization;
    attrs[0].val.programmaticStreamSerializationAllowed = 1;

    int kb = 0;
    for (int g = 0; g < G; ++g) {
        int s_min = (g - (nchunks - 1) + LAG - 1) / LAG;
        if (s_min < 0) s_min = 0;
        int s_max = g / LAG;
        if (s_max > nstrips - 1) s_max = nstrips - 1;
        if (s_max >= s_min) {
            cudaLaunchConfig_t cfg = {};
            cfg.gridDim = dim3(s_max - s_min + 1, 1, 1);
            cfg.blockDim = dim3(32, 1, 1);
            cfg.dynamicSmemBytes = 0;
            cfg.stream = 0;
            cfg.attrs = attrs;
            cfg.numAttrs = 1;
            cudaLaunchKernelEx(&cfg, dtw_chunk, x, y, N, M, g, s_min);
        }

        // Fork deskew batches whose gate launch just completed its enqueue.
        while (kb < NB && gate[kb] == g) {
            cudaEventRecord(evb[kb], 0);
            cudaStreamWaitEvent(s2, evb[kb], 0);
            dtw_deskew_band<<<dim3(4 * nty, 8), 256, 0, s2>>>(
                out, N, M, 8 * kb, qmax, nty, ntx);
            ++kb;
        }
    }

    // Join: output buffer complete only after all deskew batches finish.
    cudaEventRecord(evj, s2);
    cudaStreamWaitEvent(0, evj, 0);
}